// round 4
// baseline (speedup 1.0000x reference)
#include <cuda_runtime.h>
#include <cuda_bf16.h>
#include <mma.h>

using namespace nvcuda;

// ---------------- problem constants ----------------
constexpr int C_IN   = 320;
constexpr int HH     = 64;
constexpr int WW     = 64;
constexpr int NB     = 4;
constexpr int K_REAL = 2880;     // 320*9 (padded region of xu is zeros -> skipped)
constexpr int K_PAD  = 2944;     // weight rows still span full 2944 for amax
constexpr int O_OUT  = 384;
constexpr int RANK   = 32;
constexpr int T_TOT  = NB * HH * WW;   // 16384 tokens

// ---------------- scratch (__device__ globals; no allocations) ----------------
__device__ __nv_bfloat16 g_qxT[(size_t)K_REAL * T_TOT];  // quantized acts, K-major [k][t]
__device__ __nv_bfloat16 g_xuT[(size_t)K_REAL * T_TOT];  // fp->bf16 acts,   K-major [k][t]
__device__ __nv_bfloat16 g_qw [(size_t)O_OUT * K_REAL];  // quantized weights [o][k]
__device__ __nv_bfloat16 g_pdb[(size_t)K_REAL * RANK];   // proj_down bf16 [k][r]
__device__ float g_sw  [O_OUT];
__device__ float g_sx  [T_TOT];
__device__ float g_rsx [T_TOT];
__device__ float g_M   [T_TOT];                           // per-pixel channel max |x|
__device__ float g_r   [(size_t)T_TOT * RANK];            // lora mid  [t][r]
__device__ float g_lb  [(size_t)T_TOT * O_OUT];           // lora + bias [t][o]

// ---------------- 1) weight quantization ----------------
__global__ void k_wquant(const float* __restrict__ w) {
    int o = blockIdx.x;
    __shared__ float red[256];
    float m = 0.f;
    for (int k = threadIdx.x; k < K_PAD; k += 256)
        m = fmaxf(m, fabsf(w[(size_t)o * K_PAD + k]));
    red[threadIdx.x] = m;
    __syncthreads();
    for (int s = 128; s > 0; s >>= 1) {
        if (threadIdx.x < s) red[threadIdx.x] = fmaxf(red[threadIdx.x], red[threadIdx.x + s]);
        __syncthreads();
    }
    float sc = fmaxf(__fdiv_rn(red[0], 7.0f), 1e-8f);
    float rs = __frcp_rn(sc);
    if (threadIdx.x == 0) g_sw[o] = sc;
    for (int k = threadIdx.x; k < K_REAL; k += 256) {
        float q = rintf(w[(size_t)o * K_PAD + k] * rs);
        q = fminf(fmaxf(q, -8.f), 7.f);
        g_qw[(size_t)o * K_REAL + k] = __float2bfloat16_rn(q);
    }
}

// ---------------- 2) proj_down -> bf16 ----------------
__global__ void k_pdconv(const float* __restrict__ pd) {
    int idx = blockIdx.x * 256 + threadIdx.x;
    if (idx < K_REAL * RANK) g_pdb[idx] = __float2bfloat16_rn(pd[idx]);
}

// ---------------- 3) per-pixel channel max ----------------
__global__ void k_chanmax(const float* __restrict__ x) {
    int pos = blockIdx.x * 256 + threadIdx.x;   // 16384
    int n = pos >> 12, hw = pos & 4095;
    const float* px = x + (size_t)n * C_IN * 4096 + hw;
    float m = 0.f;
    #pragma unroll 8
    for (int c = 0; c < C_IN; c++) m = fmaxf(m, fabsf(px[(size_t)c * 4096]));
    g_M[pos] = m;
}

// ---------------- 4) per-token scales via 3x3 max-pool ----------------
__global__ void k_sx() {
    int t = blockIdx.x * 256 + threadIdx.x;     // 16384
    int n = t >> 12, h = (t >> 6) & 63, w = t & 63;
    float m = 0.f;
    #pragma unroll
    for (int dh = -1; dh <= 1; dh++) {
        int hh = h + dh;
        if (hh < 0 || hh >= HH) continue;
        #pragma unroll
        for (int dw = -1; dw <= 1; dw++) {
            int ww2 = w + dw;
            if (ww2 < 0 || ww2 >= WW) continue;
            m = fmaxf(m, g_M[(n << 12) + (hh << 6) + ww2]);
        }
    }
    float sc = fmaxf(__fdiv_rn(m, 7.0f), 1e-8f);
    g_sx[t] = sc;
    g_rsx[t] = __frcp_rn(sc);
}

// ---------------- 5) im2col + act quant (writes K-major, coalesced) ----------------
__global__ void k_imquant(const float* __restrict__ x) {
    int ho = blockIdx.x;     // 0..63
    int n  = blockIdx.y;     // 0..3
    int tid = threadIdx.x;   // 256
    __shared__ float rows[3][66];
    __shared__ float rsxs[64];
    int tokbase = (n << 12) + (ho << 6);
    if (tid < 64) rsxs[tid] = g_rsx[tokbase + tid];

    for (int c = 0; c < C_IN; c++) {
        __syncthreads();
        for (int u = tid; u < 198; u += 256) {
            int i = u / 66, wi = u % 66;         // wi 0..65 -> w = wi-1
            int hh = ho - 1 + i, wcol = wi - 1;
            float v = 0.f;
            if (hh >= 0 && hh < HH && wcol >= 0 && wcol < WW)
                v = x[(((size_t)n * C_IN + c) * HH + hh) * WW + wcol];
            rows[i][wi] = v;
        }
        __syncthreads();
        for (int u = tid; u < 576; u += 256) {
            int p = u >> 6, wo = u & 63;         // p 0..8
            float v = rows[p / 3][wo + (p % 3)];
            float q = rintf(v * rsxs[wo]);
            q = fminf(fmaxf(q, -8.f), 7.f);
            size_t off = (size_t)(c * 9 + p) * T_TOT + tokbase + wo;
            g_qxT[off] = __float2bfloat16_rn(q);
            g_xuT[off] = __float2bfloat16_rn(v);
        }
    }
}

// ---------------- 6) rank-32 GEMM: r = xu @ pd (wmma bf16) ----------------
__global__ void __launch_bounds__(128) k_rgemm() {
    int t0 = blockIdx.x * 64;
    int tid = threadIdx.x, wid = tid >> 5;
    __shared__ __nv_bfloat16 As[32][72];   // [k][m]
    __shared__ __nv_bfloat16 Bs[32][40];   // [k][r]
    wmma::fragment<wmma::accumulator, 16, 16, 16, float> acc[2];
    wmma::fill_fragment(acc[0], 0.f);
    wmma::fill_fragment(acc[1], 0.f);

    for (int k0 = 0; k0 < K_REAL; k0 += 32) {
        __syncthreads();
        #pragma unroll
        for (int u = tid; u < 256; u += 128) {
            int row = u >> 3, colc = u & 7;
            *(uint4*)&As[row][colc * 8] =
                *(const uint4*)&g_xuT[(size_t)(k0 + row) * T_TOT + t0 + colc * 8];
        }
        {
            int row = tid >> 2, colc = tid & 3;
            *(uint4*)&Bs[row][colc * 8] =
                *(const uint4*)&g_pdb[(size_t)(k0 + row) * RANK + colc * 8];
        }
        __syncthreads();
        #pragma unroll
        for (int ks = 0; ks < 32; ks += 16) {
            wmma::fragment<wmma::matrix_a, 16, 16, 16, __nv_bfloat16, wmma::col_major> a;
            wmma::load_matrix_sync(a, &As[ks][wid * 16], 72);
            #pragma unroll
            for (int ni = 0; ni < 2; ni++) {
                wmma::fragment<wmma::matrix_b, 16, 16, 16, __nv_bfloat16, wmma::row_major> b;
                wmma::load_matrix_sync(b, &Bs[ks][ni * 16], 40);
                wmma::mma_sync(acc[ni], a, b, acc[ni]);
            }
        }
    }
    #pragma unroll
    for (int ni = 0; ni < 2; ni++)
        wmma::store_matrix_sync(&g_r[(size_t)(t0 + wid * 16) * RANK + ni * 16],
                                acc[ni], RANK, wmma::mem_row_major);
}

// ---------------- 7) lora + bias: lb[t][o] = r[t] . pu[:,o] + bias[o] ----------------
__global__ void __launch_bounds__(384) k_lorabias(const float* __restrict__ pu,
                                                  const float* __restrict__ bias) {
    int o = threadIdx.x;                   // 0..383
    float puv[RANK];
    #pragma unroll
    for (int j = 0; j < RANK; j++) puv[j] = pu[j * O_OUT + o];
    float b = bias[o];
    __shared__ float rs[RANK];
    int tbase = blockIdx.x * 32;
    for (int tt = 0; tt < 32; tt++) {
        int t = tbase + tt;
        __syncthreads();
        if (o < RANK) rs[o] = g_r[(size_t)t * RANK + o];
        __syncthreads();
        float acc = b;
        #pragma unroll
        for (int j = 0; j < RANK; j++) acc += rs[j] * puv[j];
        g_lb[(size_t)t * O_OUT + o] = acc;
    }
}

// ---------------- 8) main GEMM: acc[t][o] = qx . qw (exact ints, bf16 TC) ----------------
__global__ void __launch_bounds__(256) k_gemm(float* __restrict__ out) {
    int t0  = blockIdx.x * 128;
    int oc0 = blockIdx.y * 128;
    int tid = threadIdx.x, wid = tid >> 5;
    int wm = wid & 1, wn = wid >> 1;       // 2 x 4 warps; warp tile 64 x 32
    __shared__ __nv_bfloat16 As[32][136];  // [k][m]  (A col-major)
    __shared__ __nv_bfloat16 Bs[128][40];  // [o][k]  (B col-major: B[k][n] at n*40+k)

    wmma::fragment<wmma::accumulator, 16, 16, 16, float> acc[4][2];
    #pragma unroll
    for (int mi = 0; mi < 4; mi++)
        #pragma unroll
        for (int ni = 0; ni < 2; ni++) wmma::fill_fragment(acc[mi][ni], 0.f);

    for (int k0 = 0; k0 < K_REAL; k0 += 32) {
        __syncthreads();
        #pragma unroll
        for (int u = tid; u < 512; u += 256) {
            int row = u >> 4, colc = u & 15;
            *(uint4*)&As[row][colc * 8] =
                *(const uint4*)&g_qxT[(size_t)(k0 + row) * T_TOT + t0 + colc * 8];
        }
        #pragma unroll
        for (int u = tid; u < 512; u += 256) {
            int row = u >> 2, colc = u & 3;
            *(uint4*)&Bs[row][colc * 8] =
                *(const uint4*)&g_qw[(size_t)(oc0 + row) * K_REAL + k0 + colc * 8];
        }
        __syncthreads();
        #pragma unroll
        for (int ks = 0; ks < 32; ks += 16) {
            wmma::fragment<wmma::matrix_a, 16, 16, 16, __nv_bfloat16, wmma::col_major> a[4];
            wmma::fragment<wmma::matrix_b, 16, 16, 16, __nv_bfloat16, wmma::col_major> b[2];
            #pragma unroll
            for (int mi = 0; mi < 4; mi++)
                wmma::load_matrix_sync(a[mi], &As[ks][wm * 64 + mi * 16], 136);
            #pragma unroll
            for (int ni = 0; ni < 2; ni++)
                wmma::load_matrix_sync(b[ni], &Bs[wn * 32 + ni * 16][ks], 40);
            #pragma unroll
            for (int mi = 0; mi < 4; mi++)
                #pragma unroll
                for (int ni = 0; ni < 2; ni++)
                    wmma::mma_sync(acc[mi][ni], a[mi], b[ni], acc[mi][ni]);
        }
    }
    #pragma unroll
    for (int mi = 0; mi < 4; mi++)
        #pragma unroll
        for (int ni = 0; ni < 2; ni++)
            wmma::store_matrix_sync(
                out + (size_t)(t0 + wm * 64 + mi * 16) * O_OUT + oc0 + wn * 32 + ni * 16,
                acc[mi][ni], O_OUT, wmma::mem_row_major);
}

// ---------------- 9) finalize: out = acc*sx*sw + lb ----------------
__global__ void k_finalize(float* __restrict__ out) {
    int i = blockIdx.x * 256 + threadIdx.x;   // 6,291,456 exactly
    int t = i / O_OUT, o = i - t * O_OUT;
    out[i] = out[i] * g_sx[t] * g_sw[o] + g_lb[i];
}

// ---------------- launch ----------------
extern "C" void kernel_launch(void* const* d_in, const int* in_sizes, int n_in,
                              void* d_out, int out_size) {
    (void)in_sizes; (void)n_in; (void)out_size;
    const float* x    = (const float*)d_in[0];  // (4,320,64,64)
    const float* w    = (const float*)d_in[1];  // (384,2944)
    const float* pd   = (const float*)d_in[2];  // (2944,32)
    const float* pu   = (const float*)d_in[3];  // (32,384)
    const float* bias = (const float*)d_in[4];  // (384,)
    float* out = (float*)d_out;

    k_wquant  <<<O_OUT, 256>>>(w);
    k_pdconv  <<<(K_REAL * RANK + 255) / 256, 256>>>(pd);
    k_chanmax <<<T_TOT / 256, 256>>>(x);
    k_sx      <<<T_TOT / 256, 256>>>();
    k_imquant <<<dim3(HH, NB), 256>>>(x);
    k_rgemm   <<<T_TOT / 64, 128>>>();
    k_lorabias<<<T_TOT / 32, 384>>>(pu, bias);
    k_gemm    <<<dim3(T_TOT / 128, O_OUT / 128), 256>>>(out);
    k_finalize<<<(T_TOT * O_OUT) / 256, 256>>>(out);
}

// round 8
// speedup vs baseline: 1.3264x; 1.3264x over previous
#include <cuda_runtime.h>
#include <cuda_bf16.h>
#include <mma.h>

using namespace nvcuda;

// ---------------- problem constants ----------------
constexpr int C_IN   = 320;
constexpr int HH     = 64;
constexpr int WW     = 64;
constexpr int NB     = 4;
constexpr int K_REAL = 2880;     // 320*9 (padded region of xu is zeros -> skipped)
constexpr int K_PAD  = 2944;     // weight rows still span full 2944 for amax
constexpr int O_OUT  = 384;
constexpr int RANK   = 32;
constexpr int T_TOT  = NB * HH * WW;   // 16384 tokens
constexpr int NIT    = K_REAL / 32;    // 90 K-chunks

// ---------------- scratch (__device__ globals; no allocations) ----------------
__device__ __nv_bfloat16 g_qxT[(size_t)K_REAL * T_TOT];  // quantized acts, K-major [k][t]
__device__ __nv_bfloat16 g_xuT[(size_t)K_REAL * T_TOT];  // fp->bf16 acts,   K-major [k][t]
__device__ __nv_bfloat16 g_qw [(size_t)O_OUT * K_REAL];  // quantized weights [o][k]
__device__ __nv_bfloat16 g_pdb[(size_t)K_REAL * RANK];   // proj_down bf16 [k][r]
__device__ float g_sw  [O_OUT];
__device__ float g_sx  [T_TOT];
__device__ float g_rsx [T_TOT];
__device__ float g_M   [T_TOT];                           // per-pixel channel max |x|
__device__ float g_r   [(size_t)T_TOT * RANK];            // lora mid  [t][r]
__device__ float g_lb  [(size_t)T_TOT * O_OUT];           // lora + bias [t][o]

// ---------------- cp.async helpers ----------------
__device__ __forceinline__ void cp16(void* s, const void* g) {
    unsigned saddr = (unsigned)__cvta_generic_to_shared(s);
    asm volatile("cp.async.cg.shared.global [%0], [%1], 16;\n" :: "r"(saddr), "l"(g));
}
__device__ __forceinline__ void cp_commit() {
    asm volatile("cp.async.commit_group;\n");
}
template <int N>
__device__ __forceinline__ void cp_wait() {
    asm volatile("cp.async.wait_group %0;\n" :: "n"(N));
}

// ---------------- 1) weight quantization ----------------
__global__ void k_wquant(const float* __restrict__ w) {
    int o = blockIdx.x;
    __shared__ float red[256];
    float m = 0.f;
    for (int k = threadIdx.x; k < K_PAD; k += 256)
        m = fmaxf(m, fabsf(w[(size_t)o * K_PAD + k]));
    red[threadIdx.x] = m;
    __syncthreads();
    for (int s = 128; s > 0; s >>= 1) {
        if (threadIdx.x < s) red[threadIdx.x] = fmaxf(red[threadIdx.x], red[threadIdx.x + s]);
        __syncthreads();
    }
    float sc = fmaxf(__fdiv_rn(red[0], 7.0f), 1e-8f);
    float rs = __frcp_rn(sc);
    if (threadIdx.x == 0) g_sw[o] = sc;
    for (int k = threadIdx.x; k < K_REAL; k += 256) {
        float q = rintf(w[(size_t)o * K_PAD + k] * rs);
        q = fminf(fmaxf(q, -8.f), 7.f);
        g_qw[(size_t)o * K_REAL + k] = __float2bfloat16_rn(q);
    }
}

// ---------------- 2) proj_down -> bf16 ----------------
__global__ void k_pdconv(const float* __restrict__ pd) {
    int idx = blockIdx.x * 256 + threadIdx.x;
    if (idx < K_REAL * RANK) g_pdb[idx] = __float2bfloat16_rn(pd[idx]);
}

// ---------------- 3) per-pixel channel max ----------------
__global__ void k_chanmax(const float* __restrict__ x) {
    int pos = blockIdx.x * 256 + threadIdx.x;   // 16384
    int n = pos >> 12, hw = pos & 4095;
    const float* px = x + (size_t)n * C_IN * 4096 + hw;
    float m = 0.f;
    #pragma unroll 8
    for (int c = 0; c < C_IN; c++) m = fmaxf(m, fabsf(px[(size_t)c * 4096]));
    g_M[pos] = m;
}

// ---------------- 4) per-token scales via 3x3 max-pool ----------------
__global__ void k_sx() {
    int t = blockIdx.x * 256 + threadIdx.x;     // 16384
    int n = t >> 12, h = (t >> 6) & 63, w = t & 63;
    float m = 0.f;
    #pragma unroll
    for (int dh = -1; dh <= 1; dh++) {
        int hh = h + dh;
        if (hh < 0 || hh >= HH) continue;
        #pragma unroll
        for (int dw = -1; dw <= 1; dw++) {
            int ww2 = w + dw;
            if (ww2 < 0 || ww2 >= WW) continue;
            m = fmaxf(m, g_M[(n << 12) + (hh << 6) + ww2]);
        }
    }
    float sc = fmaxf(__fdiv_rn(m, 7.0f), 1e-8f);
    g_sx[t] = sc;
    g_rsx[t] = __frcp_rn(sc);
}

// ---------------- 5) im2col + act quant, 8 channels per barrier pair ----------------
constexpr int CH = 8;
__global__ void __launch_bounds__(256) k_imquant(const float* __restrict__ x) {
    int ho = blockIdx.x;     // 0..63
    int n  = blockIdx.y;     // 0..3
    int tid = threadIdx.x;   // 256
    __shared__ float rows[CH][3][66];
    __shared__ float rsxs[64];
    int tokbase = (n << 12) + (ho << 6);
    if (tid < 64) rsxs[tid] = g_rsx[tokbase + tid];

    for (int c0 = 0; c0 < C_IN; c0 += CH) {
        __syncthreads();
        // load 8 channels x 3 halo rows x 66 cols (latencies overlap across 6+ loads/thread)
        for (int u = tid; u < CH * 198; u += 256) {
            int cc = u / 198, rem = u % 198;
            int i = rem / 66, wi = rem % 66;
            int hh = ho - 1 + i, wcol = wi - 1;
            float v = 0.f;
            if (hh >= 0 && hh < HH && (unsigned)wcol < (unsigned)WW)
                v = x[(((size_t)n * C_IN + (c0 + cc)) * HH + hh) * WW + wcol];
            rows[cc][i][wi] = v;
        }
        __syncthreads();
        for (int u = tid; u < CH * 576; u += 256) {
            int cc = u / 576, rem = u % 576;
            int p = rem >> 6, wo = rem & 63;
            float v = rows[cc][p / 3][wo + (p % 3)];
            float q = rintf(v * rsxs[wo]);
            q = fminf(fmaxf(q, -8.f), 7.f);
            size_t off = (size_t)((c0 + cc) * 9 + p) * T_TOT + tokbase + wo;
            g_qxT[off] = __float2bfloat16_rn(q);
            g_xuT[off] = __float2bfloat16_rn(v);
        }
    }
}

// ---------------- 6) rank-32 GEMM: r = xu @ pd (double-buffered cp.async) ----------------
__global__ void __launch_bounds__(128) k_rgemm() {
    int t0 = blockIdx.x * 64;
    int tid = threadIdx.x, wid = tid >> 5;
    __shared__ __align__(16) __nv_bfloat16 As[2][32][72];   // [k][m]
    __shared__ __align__(16) __nv_bfloat16 Bs[2][32][40];   // [k][r]

    wmma::fragment<wmma::accumulator, 16, 16, 16, float> acc[2];
    wmma::fill_fragment(acc[0], 0.f);
    wmma::fill_fragment(acc[1], 0.f);

    auto copy_tiles = [&](int k0, int b) {
        #pragma unroll
        for (int u = tid; u < 256; u += 128) {
            int row = u >> 3, colc = u & 7;
            cp16(&As[b][row][colc * 8],
                 &g_xuT[(size_t)(k0 + row) * T_TOT + t0 + colc * 8]);
        }
        {
            int row = tid >> 2, colc = tid & 3;
            cp16(&Bs[b][row][colc * 8],
                 &g_pdb[(size_t)(k0 + row) * RANK + colc * 8]);
        }
        cp_commit();
    };

    copy_tiles(0, 0);
    for (int it = 0; it < NIT; it++) {
        int cur = it & 1;
        if (it + 1 < NIT) { copy_tiles((it + 1) * 32, cur ^ 1); cp_wait<1>(); }
        else              { cp_wait<0>(); }
        __syncthreads();
        #pragma unroll
        for (int ks = 0; ks < 32; ks += 16) {
            wmma::fragment<wmma::matrix_a, 16, 16, 16, __nv_bfloat16, wmma::col_major> a;
            wmma::load_matrix_sync(a, &As[cur][ks][wid * 16], 72);
            #pragma unroll
            for (int ni = 0; ni < 2; ni++) {
                wmma::fragment<wmma::matrix_b, 16, 16, 16, __nv_bfloat16, wmma::row_major> b;
                wmma::load_matrix_sync(b, &Bs[cur][ks][ni * 16], 40);
                wmma::mma_sync(acc[ni], a, b, acc[ni]);
            }
        }
        __syncthreads();
    }
    #pragma unroll
    for (int ni = 0; ni < 2; ni++)
        wmma::store_matrix_sync(&g_r[(size_t)(t0 + wid * 16) * RANK + ni * 16],
                                acc[ni], RANK, wmma::mem_row_major);
}

// ---------------- 7) lora + bias: lb[t][o] = r[t] . pu[:,o] + bias[o] ----------------
__global__ void __launch_bounds__(384) k_lorabias(const float* __restrict__ pu,
                                                  const float* __restrict__ bias) {
    int o = threadIdx.x;                   // 0..383
    float puv[RANK];
    #pragma unroll
    for (int j = 0; j < RANK; j++) puv[j] = pu[j * O_OUT + o];
    float b = bias[o];
    __shared__ float rs[RANK];
    int tbase = blockIdx.x * 32;
    for (int tt = 0; tt < 32; tt++) {
        int t = tbase + tt;
        __syncthreads();
        if (o < RANK) rs[o] = g_r[(size_t)t * RANK + o];
        __syncthreads();
        float acc = b;
        #pragma unroll
        for (int j = 0; j < RANK; j++) acc += rs[j] * puv[j];
        g_lb[(size_t)t * O_OUT + o] = acc;
    }
}

// ---------------- 8) main GEMM + fused epilogue ----------------
// out[t][o] = (qx . qw) * sx[t]*sw[o] + lb[t][o]
// 128x128 tile, K-chunk 32, cp.async double-buffered, grid x = oc (A L2 reuse)
constexpr int AS_BYTES = 32 * 136 * 2;    // 8704 per buffer
constexpr int BS_BYTES = 128 * 40 * 2;    // 10240 per buffer
constexpr int SM_BYTES = 2 * AS_BYTES + 2 * BS_BYTES;   // 37888
constexpr int SCR_LDM  = 20;              // float wmma store: ldm MUST be multiple of 4

__global__ void __launch_bounds__(256) k_gemm(float* __restrict__ out) {
    int oc0 = blockIdx.x * 128;
    int t0  = blockIdx.y * 128;
    int tid = threadIdx.x, wid = tid >> 5, lane = tid & 31;
    int wm = wid & 1, wn = wid >> 1;       // 2 x 4 warps; warp tile 64 x 32

    __shared__ __align__(16) unsigned char sm[SM_BYTES];
    auto AsP = [&](int b) { return (__nv_bfloat16*)(sm + b * AS_BYTES); };
    auto BsP = [&](int b) { return (__nv_bfloat16*)(sm + 2 * AS_BYTES + b * BS_BYTES); };

    wmma::fragment<wmma::accumulator, 16, 16, 16, float> acc[4][2];
    #pragma unroll
    for (int mi = 0; mi < 4; mi++)
        #pragma unroll
        for (int ni = 0; ni < 2; ni++) wmma::fill_fragment(acc[mi][ni], 0.f);

    auto copy_tiles = [&](int k0, int b) {
        __nv_bfloat16* As = AsP(b);
        __nv_bfloat16* Bs = BsP(b);
        #pragma unroll
        for (int u = tid; u < 512; u += 256) {          // A: 32 x 128 bf16
            int row = u >> 4, colc = u & 15;
            cp16(As + row * 136 + colc * 8,
                 &g_qxT[(size_t)(k0 + row) * T_TOT + t0 + colc * 8]);
        }
        #pragma unroll
        for (int u = tid; u < 512; u += 256) {          // B: 128 x 32 bf16
            int row = u >> 2, colc = u & 3;
            cp16(Bs + row * 40 + colc * 8,
                 &g_qw[(size_t)(oc0 + row) * K_REAL + k0 + colc * 8]);
        }
        cp_commit();
    };

    copy_tiles(0, 0);
    for (int it = 0; it < NIT; it++) {
        int cur = it & 1;
        if (it + 1 < NIT) { copy_tiles((it + 1) * 32, cur ^ 1); cp_wait<1>(); }
        else              { cp_wait<0>(); }
        __syncthreads();
        __nv_bfloat16* As = AsP(cur);
        __nv_bfloat16* Bs = BsP(cur);
        #pragma unroll
        for (int ks = 0; ks < 32; ks += 16) {
            wmma::fragment<wmma::matrix_a, 16, 16, 16, __nv_bfloat16, wmma::col_major> a[4];
            wmma::fragment<wmma::matrix_b, 16, 16, 16, __nv_bfloat16, wmma::col_major> b[2];
            #pragma unroll
            for (int mi = 0; mi < 4; mi++)
                wmma::load_matrix_sync(a[mi], As + ks * 136 + wm * 64 + mi * 16, 136);
            #pragma unroll
            for (int ni = 0; ni < 2; ni++)
                wmma::load_matrix_sync(b[ni], Bs + (wn * 32 + ni * 16) * 40 + ks, 40);
            #pragma unroll
            for (int mi = 0; mi < 4; mi++)
                #pragma unroll
                for (int ni = 0; ni < 2; ni++)
                    wmma::mma_sync(acc[mi][ni], a[mi], b[ni], acc[mi][ni]);
        }
        __syncthreads();
    }

    // fused epilogue: stage each 16x16 acc tile through per-warp smem scratch
    // (ldm = 20, a multiple of 4 as required for float fragments),
    // then out = acc*sx*sw + lb
    float* scr = (float*)sm + wid * (16 * SCR_LDM);
    int r  = lane >> 1;
    int c0 = (lane & 1) * 8;
    #pragma unroll
    for (int mi = 0; mi < 4; mi++) {
        #pragma unroll
        for (int ni = 0; ni < 2; ni++) {
            wmma::store_matrix_sync(scr, acc[mi][ni], SCR_LDM, wmma::mem_row_major);
            __syncwarp();
            int t  = t0 + wm * 64 + mi * 16 + r;
            int o0 = oc0 + wn * 32 + ni * 16 + c0;
            float sxv = g_sx[t];
            const float* lbp = &g_lb[(size_t)t * O_OUT + o0];
            float* op = out + (size_t)t * O_OUT + o0;
            #pragma unroll
            for (int j = 0; j < 8; j++)
                op[j] = scr[r * SCR_LDM + c0 + j] * sxv * g_sw[o0 + j] + lbp[j];
            __syncwarp();
        }
    }
}

// ---------------- launch ----------------
extern "C" void kernel_launch(void* const* d_in, const int* in_sizes, int n_in,
                              void* d_out, int out_size) {
    (void)in_sizes; (void)n_in; (void)out_size;
    const float* x    = (const float*)d_in[0];  // (4,320,64,64)
    const float* w    = (const float*)d_in[1];  // (384,2944)
    const float* pd   = (const float*)d_in[2];  // (2944,32)
    const float* pu   = (const float*)d_in[3];  // (32,384)
    const float* bias = (const float*)d_in[4];  // (384,)
    float* out = (float*)d_out;

    k_wquant  <<<O_OUT, 256>>>(w);
    k_pdconv  <<<(K_REAL * RANK + 255) / 256, 256>>>(pd);
    k_chanmax <<<T_TOT / 256, 256>>>(x);
    k_sx      <<<T_TOT / 256, 256>>>();
    k_imquant <<<dim3(HH, NB), 256>>>(x);
    k_rgemm   <<<T_TOT / 64, 128>>>();
    k_lorabias<<<T_TOT / 32, 384>>>(pu, bias);
    k_gemm    <<<dim3(O_OUT / 128, T_TOT / 128), 256>>>(out);
}